// round 7
// baseline (speedup 1.0000x reference)
#include <cuda_runtime.h>
#include <cuda_fp16.h>

// Problem constants (fixed by the reference setup)
#define NN 262144
#define EE 4194304
#define HID 32
#define LYR 4
#define FULLM 0xffffffffu

// ---------------- device scratch (static, no allocation) ----------------
__device__ int   g_deg[NN];
__device__ int   g_offs[NN];
__device__ int   g_cursor[NN];
__device__ int   g_blocksum[256];
__device__ int   g_csr[EE];
__device__ __align__(16) __half g_h0[NN * 16];   // layer-0 input, padded 9 -> 16
__device__ __align__(16) __half g_hA[NN * 32];
__device__ __align__(16) __half g_hB[NN * 32];
__device__ __align__(16) float  g_agg[NN * 32];  // fp32 aggregation sums
__device__ __align__(16) __half g_z[NN * 32];    // pre-BN MLP output
__device__ __align__(16) float  g_acc[NN * 8];   // running cat(xs) @ lin_W + lin_b
__device__ float g_stats[LYR * 64];

// ---------------- init: h0 build (fp16) + zero deg/stats ----------------
__global__ void k_init(const float* __restrict__ x, const float* __restrict__ t) {
    int idx = blockIdx.x * blockDim.x + threadIdx.x;
    if (idx < NN * 16) {
        int i = idx >> 4, c = idx & 15;
        float v = 0.f;
        if (c < 8)       v = x[i * 8 + c];
        else if (c == 8) v = t[0];
        g_h0[idx] = __float2half_rn(v);
    }
    if (idx < NN) g_deg[idx] = 0;
    if (idx < LYR * 64) g_stats[idx] = 0.f;
}

// ---------------- CSR build ----------------
__global__ void k_hist(const int* __restrict__ ei) {
    int e4 = blockIdx.x * blockDim.x + threadIdx.x;
    if (e4 < EE / 4) {
        int4 d = __ldg(&((const int4*)(ei + EE))[e4]);
        atomicAdd(&g_deg[d.x], 1);
        atomicAdd(&g_deg[d.y], 1);
        atomicAdd(&g_deg[d.z], 1);
        atomicAdd(&g_deg[d.w], 1);
    }
}

__global__ void k_scan1() {
    int tid = threadIdx.x, lane = tid & 31, wid = tid >> 5;
    int g = blockIdx.x * 1024 + tid;
    int v = g_deg[g];
    int xv = v;
#pragma unroll
    for (int off = 1; off < 32; off <<= 1) {
        int y = __shfl_up_sync(FULLM, xv, off);
        if (lane >= off) xv += y;
    }
    __shared__ int wt[32];
    if (lane == 31) wt[wid] = xv;
    __syncthreads();
    if (wid == 0) {
        int w = wt[lane];
        int xi = w;
#pragma unroll
        for (int off = 1; off < 32; off <<= 1) {
            int y = __shfl_up_sync(FULLM, xi, off);
            if (lane >= off) xi += y;
        }
        wt[lane] = xi - w;
        if (lane == 31) g_blocksum[blockIdx.x] = xi;
    }
    __syncthreads();
    g_offs[g] = (xv - v) + wt[wid];
}

__global__ void k_scan2() {
    int tid = threadIdx.x, lane = tid & 31, wid = tid >> 5;
    int v = g_blocksum[tid];
    int xv = v;
#pragma unroll
    for (int off = 1; off < 32; off <<= 1) {
        int y = __shfl_up_sync(FULLM, xv, off);
        if (lane >= off) xv += y;
    }
    __shared__ int wt[8];
    if (lane == 31) wt[wid] = xv;
    __syncthreads();
    if (tid == 0) {
        int s = 0;
        for (int i = 0; i < 8; i++) { int t0 = wt[i]; wt[i] = s; s += t0; }
    }
    __syncthreads();
    int out = (xv - v) + wt[wid];
    __syncthreads();
    g_blocksum[tid] = out;
}

__global__ void k_scan3() {
    int g = blockIdx.x * blockDim.x + threadIdx.x;
    if (g < NN) {
        int o = g_offs[g] + g_blocksum[g >> 10];
        g_offs[g] = o;
        g_cursor[g] = o;
    }
}

__global__ void k_fill(const int* __restrict__ ei) {
    int e4 = blockIdx.x * blockDim.x + threadIdx.x;
    if (e4 < EE / 4) {
        int4 s = __ldg(&((const int4*)ei)[e4]);
        int4 d = __ldg(&((const int4*)(ei + EE))[e4]);
        g_csr[atomicAdd(&g_cursor[d.x], 1)] = s.x;
        g_csr[atomicAdd(&g_cursor[d.y], 1)] = s.y;
        g_csr[atomicAdd(&g_cursor[d.z], 1)] = s.z;
        g_csr[atomicAdd(&g_cursor[d.w], 1)] = s.w;
    }
}

// ---------------- helpers ----------------
__device__ __forceinline__ void acc8(float* a, uint4 v) {
    float2 f0 = __half22float2(*reinterpret_cast<__half2*>(&v.x));
    float2 f1 = __half22float2(*reinterpret_cast<__half2*>(&v.y));
    float2 f2 = __half22float2(*reinterpret_cast<__half2*>(&v.z));
    float2 f3 = __half22float2(*reinterpret_cast<__half2*>(&v.w));
    a[0] += f0.x; a[1] += f0.y; a[2] += f1.x; a[3] += f1.y;
    a[4] += f2.x; a[5] += f2.y; a[6] += f3.x; a[7] += f3.y;
}

// ---------------- aggregation: agg[i] = (1+eps)*h[i] + sum_{j->i} h[j] -----
// STRIDE = halves per row (16 or 32). Row = ROWV uint4 loads (8 halves each).
// Warp split into G = 32/ROWV groups; each group fetches one edge row slice.
template <int STRIDE>
__global__ __launch_bounds__(256) void k_agg(
    const __half* __restrict__ h_in, float* __restrict__ agg_out,
    const float* __restrict__ eps_p, int layer)
{
    constexpr int ROWV = STRIDE / 8;   // uint4 per row: 2 (L0) or 4
    constexpr int G    = 32 / ROWV;    // edges per warp instr: 16 or 8
    float epsv = 1.0f + eps_p[layer];

    int tid = threadIdx.x;
    int lane = tid & 31, wid = tid >> 5;
    int grp  = lane / ROWV;
    int r    = lane & (ROWV - 1);
    int w  = blockIdx.x * (blockDim.x >> 5) + wid;
    int nw = gridDim.x * (blockDim.x >> 5);

    const uint4* hin = (const uint4*)h_in;
    float4* agg4 = (float4*)agg_out;

    for (int i = w; i < NN; i += nw) {
        float a[8], b[8];
#pragma unroll
        for (int q = 0; q < 8; q++) { a[q] = 0.f; b[q] = 0.f; }
        if (grp == 0) {
            uint4 s = __ldg(&hin[i * ROWV + r]);
            acc8(a, s);
#pragma unroll
            for (int q = 0; q < 8; q++) a[q] *= epsv;
        }

        int start = g_offs[i];
        int end   = (i + 1 < NN) ? g_offs[i + 1] : EE;

        for (int j0 = start; j0 < end; j0 += 32) {
            int myj = j0 + lane;
            int idx = (myj < end) ? g_csr[myj] : 0;
            int cnt = min(32, end - j0);
            int k = 0;
            for (; k + 2 * G <= cnt; k += 2 * G) {
                int s0 = __shfl_sync(FULLM, idx, k + grp);
                int s1 = __shfl_sync(FULLM, idx, k + G + grp);
                uint4 v0 = __ldg(&hin[s0 * ROWV + r]);
                uint4 v1 = __ldg(&hin[s1 * ROWV + r]);
                acc8(a, v0);
                acc8(b, v1);
            }
            for (; k < cnt; k += G) {
                int e = k + grp;
                int s = __shfl_sync(FULLM, idx, e & 31);
                if (e < cnt) {
                    uint4 v = __ldg(&hin[s * ROWV + r]);
                    acc8(a, v);
                }
            }
        }
#pragma unroll
        for (int q = 0; q < 8; q++) a[q] += b[q];

        // fold groups: xor-reduce so lanes with grp==0 hold totals for slice r
#pragma unroll
        for (int off = ROWV; off < 32; off <<= 1) {
#pragma unroll
            for (int q = 0; q < 8; q++)
                a[q] += __shfl_xor_sync(FULLM, a[q], off);
        }
        if (grp == 0) {
            float4 lo = make_float4(a[0], a[1], a[2], a[3]);
            float4 hi = make_float4(a[4], a[5], a[6], a[7]);
            agg4[i * (STRIDE / 4) + r * 2 + 0] = lo;
            agg4[i * (STRIDE / 4) + r * 2 + 1] = hi;
        }
    }
}

// ---------------- MLP + BN stats: z = relu(agg@W1+b1)@W2+b2 -----------------
// Warp per node; lane = output channel; weights in registers. STRIDE = floats
// per agg row (16 or 32).
template <int STRIDE>
__global__ __launch_bounds__(256) void k_mlp(
    const float* __restrict__ agg, __half* __restrict__ z_out,
    const float* __restrict__ W1, int w1rows, const float* __restrict__ b1,
    const float* __restrict__ W2, const float* __restrict__ b2, int layer)
{
    __shared__ float hs[8][32];
    __shared__ float rs[8][32], rq[8][32];

    int tid = threadIdx.x;
    int lane = tid & 31, wid = tid >> 5;

    float w1r[STRIDE], w2r[32];
#pragma unroll
    for (int c = 0; c < STRIDE; c++)
        w1r[c] = (c < w1rows) ? __ldg(&W1[c * 32 + lane]) : 0.f;
#pragma unroll
    for (int c = 0; c < 32; c++)
        w2r[c] = __ldg(&W2[c * 32 + lane]);
    float b1v = __ldg(&b1[lane]);
    float b2v = __ldg(&b2[lane]);

    int w  = blockIdx.x * (blockDim.x >> 5) + wid;
    int nw = gridDim.x * (blockDim.x >> 5);
    float ssum = 0.f, ssq = 0.f;

    const float4* agg4 = (const float4*)agg;

    for (int i = w; i < NN; i += nw) {
        float hid = b1v;
#pragma unroll
        for (int q = 0; q < STRIDE / 4; q++) {
            float4 a = __ldg(&agg4[i * (STRIDE / 4) + q]);
            hid = fmaf(a.x, w1r[4 * q + 0], hid);
            hid = fmaf(a.y, w1r[4 * q + 1], hid);
            hid = fmaf(a.z, w1r[4 * q + 2], hid);
            hid = fmaf(a.w, w1r[4 * q + 3], hid);
        }
        hid = fmaxf(hid, 0.f);

        hs[wid][lane] = hid;
        __syncwarp();
        float o = b2v;
        const float4* hrow = (const float4*)&hs[wid][0];
#pragma unroll
        for (int q = 0; q < 8; q++) {
            float4 hq = hrow[q];
            o = fmaf(hq.x, w2r[4 * q + 0], o);
            o = fmaf(hq.y, w2r[4 * q + 1], o);
            o = fmaf(hq.z, w2r[4 * q + 2], o);
            o = fmaf(hq.w, w2r[4 * q + 3], o);
        }
        __syncwarp();
        z_out[i * 32 + lane] = __float2half_rn(o);
        ssum += o;
        ssq  = fmaf(o, o, ssq);
    }

    rs[wid][lane] = ssum;
    rq[wid][lane] = ssq;
    __syncthreads();
    if (wid == 0) {
        float s = 0.f, q = 0.f;
#pragma unroll
        for (int ww = 0; ww < 8; ww++) { s += rs[ww][lane]; q += rq[ww][lane]; }
        atomicAdd(&g_stats[layer * 64 + lane], s);
        atomicAdd(&g_stats[layer * 64 + 32 + lane], q);
    }
}

// ---------------- BN apply + ReLU + incremental final linear ----------------
__global__ __launch_bounds__(256) void k_bn(
    const __half* __restrict__ z, __half* __restrict__ h_out,
    const float* __restrict__ gamma, const float* __restrict__ beta,
    const float* __restrict__ linW, const float* __restrict__ lin_b,
    int layer)
{
    __shared__ float sc[32], bi[32], lw[256];
    int tid = threadIdx.x;
    if (tid < 32) {
        float s = g_stats[layer * 64 + tid];
        float q = g_stats[layer * 64 + 32 + tid];
        float mu  = s * (1.0f / NN);
        float var = q * (1.0f / NN) - mu * mu;
        float inv = rsqrtf(var + 1e-5f);
        float g = gamma[layer * 32 + tid] * inv;
        sc[tid] = g;
        bi[tid] = beta[layer * 32 + tid] - mu * g;
    }
    for (int i = tid; i < 256; i += blockDim.x) lw[i] = linW[layer * 256 + i];
    __syncthreads();

    int lane = tid & 31, wid = tid >> 5;
    int w  = blockIdx.x * (blockDim.x >> 5) + wid;
    int nw = gridDim.x * (blockDim.x >> 5);
    for (int i = w; i < NN; i += nw) {
        float zv = __half2float(z[i * 32 + lane]);
        float h = fmaxf(fmaf(zv, sc[lane], bi[lane]), 0.f);
        h_out[i * 32 + lane] = __float2half_rn(h);
        float od[8];
#pragma unroll
        for (int d = 0; d < 8; d++) {
            float p = h * lw[lane * 8 + d];
#pragma unroll
            for (int off = 16; off; off >>= 1)
                p += __shfl_xor_sync(FULLM, p, off);
            od[d] = p;
        }
        if (lane < 8) {
            float v = od[lane];
            if (layer == 0) v += lin_b[lane];
            else            v += g_acc[i * 8 + lane];
            g_acc[i * 8 + lane] = v;
        }
    }
}

// ---------------- masked write-back (masks are int32) ----------------
__global__ void k_mask(const float* __restrict__ x,
                       const int* __restrict__ nm,
                       const int* __restrict__ em,
                       float* __restrict__ out)
{
    int idx = blockIdx.x * blockDim.x + threadIdx.x;
    if (idx < NN * 8) {
        int i = idx >> 3, c = idx & 7;
        bool wn = (nm[i] != 0) && (c >= 1 && c <= 5);
        bool we = (em[i] != 0) && (c >= 1 && c <= 4);
        out[idx] = (wn || we) ? g_acc[idx] : x[idx];
    }
}

// ---------------- launch ----------------
extern "C" void kernel_launch(void* const* d_in, const int* in_sizes, int n_in,
                              void* d_out, int out_size)
{
    const float* x        = (const float*)d_in[0];
    const float* t        = (const float*)d_in[1];
    const int*   ei       = (const int*)d_in[2];
    const int*   node_mask = (const int*)d_in[3];
    const int*   edge_mask = (const int*)d_in[4];
    const float* W1_first = (const float*)d_in[7];
    const float* b1_first = (const float*)d_in[8];
    const float* W2_first = (const float*)d_in[9];
    const float* b2_first = (const float*)d_in[10];
    const float* W1_rest  = (const float*)d_in[11];
    const float* b1_rest  = (const float*)d_in[12];
    const float* W2_rest  = (const float*)d_in[13];
    const float* b2_rest  = (const float*)d_in[14];
    const float* eps      = (const float*)d_in[15];
    const float* bn_gamma = (const float*)d_in[16];
    const float* bn_beta  = (const float*)d_in[17];
    const float* lin_W    = (const float*)d_in[18];
    const float* lin_b    = (const float*)d_in[19];
    float* out = (float*)d_out;

    k_init<<<(NN * 16 + 255) / 256, 256>>>(x, t);
    k_hist<<<(EE / 4 + 255) / 256, 256>>>(ei);
    k_scan1<<<256, 1024>>>();
    k_scan2<<<1, 256>>>();
    k_scan3<<<(NN + 255) / 256, 256>>>();
    k_fill<<<(EE / 4 + 255) / 256, 256>>>(ei);

    const int GB = 148 * 8;

    __half* h0; cudaGetSymbolAddress((void**)&h0, g_h0);
    float*  ag; cudaGetSymbolAddress((void**)&ag, g_agg);
    __half* zz; cudaGetSymbolAddress((void**)&zz, g_z);
    __half* hA; cudaGetSymbolAddress((void**)&hA, g_hA);
    __half* hB; cudaGetSymbolAddress((void**)&hB, g_hB);

    // Layer 0
    k_agg<16><<<GB, 256>>>(h0, ag, eps, 0);
    k_mlp<16><<<GB, 256>>>(ag, zz, W1_first, 9, b1_first, W2_first, b2_first, 0);
    k_bn<<<GB, 256>>>(zz, hA, bn_gamma, bn_beta, lin_W, lin_b, 0);

    // Layer 1
    k_agg<32><<<GB, 256>>>(hA, ag, eps, 1);
    k_mlp<32><<<GB, 256>>>(ag, zz, W1_rest + 0 * 1024, 32, b1_rest + 0 * 32,
                           W2_rest + 0 * 1024, b2_rest + 0 * 32, 1);
    k_bn<<<GB, 256>>>(zz, hB, bn_gamma, bn_beta, lin_W, lin_b, 1);

    // Layer 2
    k_agg<32><<<GB, 256>>>(hB, ag, eps, 2);
    k_mlp<32><<<GB, 256>>>(ag, zz, W1_rest + 1 * 1024, 32, b1_rest + 1 * 32,
                           W2_rest + 1 * 1024, b2_rest + 1 * 32, 2);
    k_bn<<<GB, 256>>>(zz, hA, bn_gamma, bn_beta, lin_W, lin_b, 2);

    // Layer 3
    k_agg<32><<<GB, 256>>>(hA, ag, eps, 3);
    k_mlp<32><<<GB, 256>>>(ag, zz, W1_rest + 2 * 1024, 32, b1_rest + 2 * 32,
                           W2_rest + 2 * 1024, b2_rest + 2 * 32, 3);
    k_bn<<<GB, 256>>>(zz, hB, bn_gamma, bn_beta, lin_W, lin_b, 3);

    k_mask<<<(NN * 8 + 255) / 256, 256>>>(x, node_mask, edge_mask, out);
}